// round 6
// baseline (speedup 1.0000x reference)
#include <cuda_runtime.h>
#include <float.h>

// SparseSoftmax: masked softmax over last axis of (32, 2048, 2048) fp32
// with int32 mask (mask = OD != 0). Fully-masked rows -> zeros.
//
// R6: 2 rows per CTA (256 threads). Warps 0-3 own row A, warps 4-7 own row B;
// 16 elements/thread (4 float4 + 4 int4 front-batched => MLP_p1 = 8, the
// empirically best per-warp MLP). Mask folded to -inf at load time.
// Grid halves to 32768 (less dispatch overhead / shorter launch tail); byte
// traffic unchanged (we're pinned at the ~7.05 TB/s LTS cap).

#define ROW_LEN   2048
#define THREADS   256
#define TPR       128              // threads per row
#define EPT       16
#define WARPS_PER_ROW 4

__global__ __launch_bounds__(THREADS)
void sparse_softmax_kernel(const float* __restrict__ f,
                           const int* __restrict__ od,
                           float* __restrict__ out)
{
    const int t       = threadIdx.x;
    const int subrow  = t >> 7;            // 0 or 1
    const int rt      = t & (TPR - 1);     // thread index within row
    const int row     = blockIdx.x * 2 + subrow;
    const size_t base = (size_t)row * ROW_LEN;

    const float4* __restrict__ f4 = reinterpret_cast<const float4*>(f + base);
    const int4*   __restrict__ o4 = reinterpret_cast<const int4*>(od + base);
    float4* __restrict__ out4 = reinterpret_cast<float4*>(out + base);

    const int warp      = t >> 5;          // 0..7
    const int warp_in_r = warp & 3;        // 0..3 within this row's group
    const int lane      = t & 31;
    const float NEG_INF = __int_as_float(0xff800000);

    // Front-batched loads: 4x LDG.128 features + 4x LDG.128 mask.
    float4 v0 = __ldcs(&f4[rt]);
    float4 v1 = __ldcs(&f4[rt + TPR]);
    float4 v2 = __ldcs(&f4[rt + 2 * TPR]);
    float4 v3 = __ldcs(&f4[rt + 3 * TPR]);
    int4   m0 = __ldcs(&o4[rt]);
    int4   m1 = __ldcs(&o4[rt + TPR]);
    int4   m2 = __ldcs(&o4[rt + 2 * TPR]);
    int4   m3 = __ldcs(&o4[rt + 3 * TPR]);

    // Fold mask into values: masked-out lanes become -inf.
    float vals[EPT];
    vals[ 0] = m0.x ? v0.x : NEG_INF;  vals[ 1] = m0.y ? v0.y : NEG_INF;
    vals[ 2] = m0.z ? v0.z : NEG_INF;  vals[ 3] = m0.w ? v0.w : NEG_INF;
    vals[ 4] = m1.x ? v1.x : NEG_INF;  vals[ 5] = m1.y ? v1.y : NEG_INF;
    vals[ 6] = m1.z ? v1.z : NEG_INF;  vals[ 7] = m1.w ? v1.w : NEG_INF;
    vals[ 8] = m2.x ? v2.x : NEG_INF;  vals[ 9] = m2.y ? v2.y : NEG_INF;
    vals[10] = m2.z ? v2.z : NEG_INF;  vals[11] = m2.w ? v2.w : NEG_INF;
    vals[12] = m3.x ? v3.x : NEG_INF;  vals[13] = m3.y ? v3.y : NEG_INF;
    vals[14] = m3.z ? v3.z : NEG_INF;  vals[15] = m3.w ? v3.w : NEG_INF;

    __shared__ float smax[2][WARPS_PER_ROW];
    __shared__ float ssum[2][WARPS_PER_ROW];

    // --- max reduce (per row) ---
    float mx = NEG_INF;
    #pragma unroll
    for (int i = 0; i < EPT; i++) mx = fmaxf(mx, vals[i]);
    #pragma unroll
    for (int o = 16; o > 0; o >>= 1)
        mx = fmaxf(mx, __shfl_xor_sync(0xffffffffu, mx, o));
    if (lane == 0) smax[subrow][warp_in_r] = mx;
    __syncthreads();

    float rowmax = smax[subrow][0];
    #pragma unroll
    for (int w = 1; w < WARPS_PER_ROW; w++)
        rowmax = fmaxf(rowmax, smax[subrow][w]);
    // Fully-masked row: rowmax = -inf would give NaN in (v - rowmax); clamp.
    if (!(rowmax > NEG_INF)) rowmax = 0.0f;

    // --- exp + sum; exp(-inf - rowmax) = 0 on masked lanes ---
    float sum = 0.0f;
    #pragma unroll
    for (int i = 0; i < EPT; i++) {
        vals[i] = __expf(vals[i] - rowmax);
        sum += vals[i];
    }
    #pragma unroll
    for (int o = 16; o > 0; o >>= 1)
        sum += __shfl_xor_sync(0xffffffffu, sum, o);
    if (lane == 0) ssum[subrow][warp_in_r] = sum;
    __syncthreads();

    float s = ssum[subrow][0];
    #pragma unroll
    for (int w = 1; w < WARPS_PER_ROW; w++) s += ssum[subrow][w];
    const float inv = (s > 0.0f) ? (1.0f / s) : 0.0f;   // fully-masked -> zeros

    // --- normalize + streaming writes (4x STG.128) ---
    __stcs(&out4[rt],
           make_float4(vals[0]*inv, vals[1]*inv, vals[2]*inv, vals[3]*inv));
    __stcs(&out4[rt + TPR],
           make_float4(vals[4]*inv, vals[5]*inv, vals[6]*inv, vals[7]*inv));
    __stcs(&out4[rt + 2 * TPR],
           make_float4(vals[8]*inv, vals[9]*inv, vals[10]*inv, vals[11]*inv));
    __stcs(&out4[rt + 3 * TPR],
           make_float4(vals[12]*inv, vals[13]*inv, vals[14]*inv, vals[15]*inv));
}

extern "C" void kernel_launch(void* const* d_in, const int* in_sizes, int n_in,
                              void* d_out, int out_size)
{
    const float* features = (const float*)d_in[0];
    const int*   OD       = (const int*)d_in[1];
    float*       out      = (float*)d_out;

    const int rows = in_sizes[0] / ROW_LEN;   // 32*2048 = 65536
    sparse_softmax_kernel<<<rows / 2, THREADS>>>(features, OD, out);
}